// round 12
// baseline (speedup 1.0000x reference)
#include <cuda_runtime.h>

// Problem constants
#define PB 2
#define PS 2048
#define PD 1024
#define PH 16
#define PDH 64
#define PBS (PB * PS)                        // 4096 rows
#define OUT_ELEMS ((long long)PB * PS * PD)  // 4194304

typedef unsigned long long u64;

// ---- packed fp32x2 helpers (Blackwell FFMA2 path) -------------------------
__device__ __forceinline__ u64 dup2(float x) {
    u64 r;
    asm("mov.b64 %0, {%1, %1};" : "=l"(r) : "f"(x));
    return r;
}
__device__ __forceinline__ void unpack2(u64 p, float& lo, float& hi) {
    asm("mov.b64 {%0, %1}, %2;" : "=f"(lo), "=f"(hi) : "l"(p));
}
__device__ __forceinline__ void ffma2(u64& d, u64 a, u64 b) {
    asm("fma.rn.f32x2 %0, %1, %2, %0;" : "+l"(d) : "l"(a), "l"(b));
}

// Scratch (device globals; no allocation allowed)
__device__ float g_Q[(size_t)PB * PH * PS * PDH];   // [b][h][s][k]
__device__ float g_K[(size_t)PB * PH * PS * PDH];
__device__ float g_V[(size_t)PB * PH * PS * PDH];
__device__ float g_ctx[(size_t)PB * PS * PD];       // [b][s][h*64+k]

// ---------------------------------------------------------------------------
// Kernel 1: fused Q/K/V per-head projections (packed f32x2 math).
// ---------------------------------------------------------------------------
__global__ __launch_bounds__(256) void qkv_proj_kernel(
    const float* __restrict__ q, const float* __restrict__ k,
    const float* __restrict__ v, const float* __restrict__ Wq,
    const float* __restrict__ Wk, const float* __restrict__ Wv,
    const float* __restrict__ bq, const float* __restrict__ bk,
    const float* __restrict__ bv)
{
    __shared__ float As[16][132];   // transposed: As[kk][m]
    __shared__ float Bs[16][128];   // Bs[kk][j]

    const int zz = blockIdx.z;
    const float* A    = (zz == 0) ? q  : (zz == 1) ? k  : v;
    const float* W    = (zz == 0) ? Wq : (zz == 1) ? Wk : Wv;
    const float* bias = (zz == 0) ? bq : (zz == 1) ? bk : bv;
    float* outp       = (zz == 0) ? g_Q : (zz == 1) ? g_K : g_V;
    const float scale = (zz == 0) ? 0.125f : 1.0f;   // 1/sqrt(DH) folded into Q

    const int m0 = blockIdx.x * 128;
    const int h0 = blockIdx.y * 2;
    const int tid = threadIdx.x;
    const int tx = tid & 15;
    const int ty = tid >> 4;

    u64 acc[8][4];                  // [i][j2], packed pair over j
#pragma unroll
    for (int i = 0; i < 8; i++)
#pragma unroll
        for (int j2 = 0; j2 < 4; j2++) acc[i][j2] = 0ull;

    for (int d0 = 0; d0 < PD; d0 += 16) {
#pragma unroll
        for (int l = 0; l < 2; l++) {
            int f = tid + 256 * l;
            int m = f >> 2, c4 = (f & 3) * 4;
            float4 av = *(const float4*)(A + (size_t)(m0 + m) * PD + d0 + c4);
            As[c4 + 0][m] = av.x; As[c4 + 1][m] = av.y;
            As[c4 + 2][m] = av.z; As[c4 + 3][m] = av.w;
        }
#pragma unroll
        for (int l = 0; l < 2; l++) {
            int f = tid + 256 * l;
            int kk = f >> 5, c4 = (f & 31) * 4;
            int hh = h0 + (c4 >> 6);
            int kc = c4 & 63;
            *(float4*)&Bs[kk][c4] =
                *(const float4*)(W + ((size_t)hh * PD + (d0 + kk)) * PDH + kc);
        }
        __syncthreads();
#pragma unroll
        for (int kk = 0; kk < 16; kk++) {
            float a[8];
            *(float4*)&a[0] = *(const float4*)&As[kk][ty * 8];
            *(float4*)&a[4] = *(const float4*)&As[kk][ty * 8 + 4];
            ulonglong2 bb0 = *(const ulonglong2*)&Bs[kk][tx * 8];
            ulonglong2 bb1 = *(const ulonglong2*)&Bs[kk][tx * 8 + 4];
            u64 b2[4] = {bb0.x, bb0.y, bb1.x, bb1.y};
            u64 a2[8];
#pragma unroll
            for (int i = 0; i < 8; i++) a2[i] = dup2(a[i]);
#pragma unroll
            for (int i = 0; i < 8; i++)
#pragma unroll
                for (int j2 = 0; j2 < 4; j2++) ffma2(acc[i][j2], a2[i], b2[j2]);
        }
        __syncthreads();
    }

    const int jbase = tx * 8;
    const int hh = h0 + (jbase >> 6);
    const int kc0 = jbase & 63;
    float bcol[8];
#pragma unroll
    for (int j = 0; j < 8; j++) bcol[j] = bias[hh * PDH + kc0 + j];

#pragma unroll
    for (int i = 0; i < 8; i++) {
        int r = m0 + ty * 8 + i;
        int bb_ = r >> 11;
        int s = r & (PS - 1);
        float* dst = outp + ((size_t)(bb_ * PH + hh) * PS + s) * PDH + kc0;
        float o[8];
#pragma unroll
        for (int j2 = 0; j2 < 4; j2++) unpack2(acc[i][j2], o[2 * j2], o[2 * j2 + 1]);
#pragma unroll
        for (int j = 0; j < 8; j++) o[j] = (o[j] + bcol[j]) * scale;
        *(float4*)dst       = *(float4*)&o[0];
        *(float4*)(dst + 4) = *(float4*)&o[4];
    }
}

// ---------------------------------------------------------------------------
// Kernel 2: raw scores = Qh * Kh^T into aws[h][b][:, :] (packed f32x2 math).
// ---------------------------------------------------------------------------
__global__ __launch_bounds__(256) void scores_kernel(float* __restrict__ aw)
{
    __shared__ float As[16][132];
    __shared__ float Bs[16][132];

    const int zz = blockIdx.z;           // b*H + h
    const int b_ = zz >> 4, h_ = zz & 15;
    const float* Qh = g_Q + (size_t)zz * PS * PDH;
    const float* Kh = g_K + (size_t)zz * PS * PDH;
    float* awb = aw + (size_t)(h_ * PB + b_) * PS * PS;

    const int m0 = blockIdx.x * 128;
    const int n0 = blockIdx.y * 128;
    const int tid = threadIdx.x;
    const int tx = tid & 15, ty = tid >> 4;

    u64 acc[8][4];
#pragma unroll
    for (int i = 0; i < 8; i++)
#pragma unroll
        for (int j2 = 0; j2 < 4; j2++) acc[i][j2] = 0ull;

    for (int d0 = 0; d0 < PDH; d0 += 16) {
#pragma unroll
        for (int l = 0; l < 2; l++) {
            int f = tid + 256 * l;
            int m = f >> 2, c4 = (f & 3) * 4;
            float4 av = *(const float4*)(Qh + (size_t)(m0 + m) * PDH + d0 + c4);
            As[c4 + 0][m] = av.x; As[c4 + 1][m] = av.y;
            As[c4 + 2][m] = av.z; As[c4 + 3][m] = av.w;
            float4 kv = *(const float4*)(Kh + (size_t)(n0 + m) * PDH + d0 + c4);
            Bs[c4 + 0][m] = kv.x; Bs[c4 + 1][m] = kv.y;
            Bs[c4 + 2][m] = kv.z; Bs[c4 + 3][m] = kv.w;
        }
        __syncthreads();
#pragma unroll
        for (int kk = 0; kk < 16; kk++) {
            float a[8];
            *(float4*)&a[0] = *(const float4*)&As[kk][ty * 8];
            *(float4*)&a[4] = *(const float4*)&As[kk][ty * 8 + 4];
            ulonglong2 bb0 = *(const ulonglong2*)&Bs[kk][tx * 8];
            ulonglong2 bb1 = *(const ulonglong2*)&Bs[kk][tx * 8 + 4];
            u64 b2[4] = {bb0.x, bb0.y, bb1.x, bb1.y};
            u64 a2[8];
#pragma unroll
            for (int i = 0; i < 8; i++) a2[i] = dup2(a[i]);
#pragma unroll
            for (int i = 0; i < 8; i++)
#pragma unroll
                for (int j2 = 0; j2 < 4; j2++) ffma2(acc[i][j2], a2[i], b2[j2]);
        }
        __syncthreads();
    }

#pragma unroll
    for (int i = 0; i < 8; i++) {
        int qi = m0 + ty * 8 + i;
        float* dst = awb + (size_t)qi * PS + n0 + tx * 8;
        float o[8];
#pragma unroll
        for (int j2 = 0; j2 < 4; j2++) unpack2(acc[i][j2], o[2 * j2], o[2 * j2 + 1]);
        *(float4*)dst       = *(float4*)&o[0];
        *(float4*)(dst + 4) = *(float4*)&o[4];
    }
}

// ---------------------------------------------------------------------------
// Kernel 3: in-place row softmax over aws (unchanged — memory bound).
// ---------------------------------------------------------------------------
__global__ __launch_bounds__(256) void softmax_kernel(float* __restrict__ aw)
{
    float* p = aw + (size_t)blockIdx.x * PS;
    const int t = threadIdx.x;
    const int lane = t & 31, warp = t >> 5;

    float x[8];
    *(float4*)&x[0] = ((const float4*)p)[t];
    *(float4*)&x[4] = ((const float4*)p)[t + 256];

    float m = x[0];
#pragma unroll
    for (int i = 1; i < 8; i++) m = fmaxf(m, x[i]);
#pragma unroll
    for (int o = 16; o > 0; o >>= 1) m = fmaxf(m, __shfl_xor_sync(0xffffffffu, m, o));

    __shared__ float red[8];
    if (lane == 0) red[warp] = m;
    __syncthreads();
    float mm = red[0];
#pragma unroll
    for (int i = 1; i < 8; i++) mm = fmaxf(mm, red[i]);

    float ssum = 0.f;
#pragma unroll
    for (int i = 0; i < 8; i++) { x[i] = __expf(x[i] - mm); ssum += x[i]; }
#pragma unroll
    for (int o = 16; o > 0; o >>= 1) ssum += __shfl_xor_sync(0xffffffffu, ssum, o);

    __syncthreads();
    if (lane == 0) red[warp] = ssum;
    __syncthreads();
    float tot = 0.f;
#pragma unroll
    for (int i = 0; i < 8; i++) tot += red[i];
    float inv = 1.0f / tot;
#pragma unroll
    for (int i = 0; i < 8; i++) x[i] *= inv;

    ((float4*)p)[t]       = *(float4*)&x[0];
    ((float4*)p)[t + 256] = *(float4*)&x[4];
}

// ---------------------------------------------------------------------------
// Kernel 4: ctx = aw * V per (b,h). Packed f32x2 along the i (row) dimension:
// a-pairs are contiguous in the transposed smem tile; b duplicated (4/kk).
// ---------------------------------------------------------------------------
__global__ __launch_bounds__(256) void ctx_kernel(const float* __restrict__ aw)
{
    __shared__ float As[16][132];   // transposed aw tile: As[kk][m]
    __shared__ float Bs[16][64];    // V tile, natural layout

    const int zz = blockIdx.z;
    const int b_ = zz >> 4, h_ = zz & 15;
    const float* awb = aw + (size_t)(h_ * PB + b_) * PS * PS;
    const float* Vh = g_V + (size_t)zz * PS * PDH;

    const int m0 = blockIdx.x * 128;
    const int tid = threadIdx.x;
    const int tx = tid & 15, ty = tid >> 4;

    u64 acc[4][4];                  // [i2][j]: lo=row 2*i2, hi=row 2*i2+1
#pragma unroll
    for (int i2 = 0; i2 < 4; i2++)
#pragma unroll
        for (int j = 0; j < 4; j++) acc[i2][j] = 0ull;

    for (int kc = 0; kc < PS; kc += 16) {
#pragma unroll
        for (int l = 0; l < 2; l++) {
            int f = tid + 256 * l;
            int m = f >> 2, c4 = (f & 3) * 4;
            float4 av = *(const float4*)(awb + (size_t)(m0 + m) * PS + kc + c4);
            As[c4 + 0][m] = av.x; As[c4 + 1][m] = av.y;
            As[c4 + 2][m] = av.z; As[c4 + 3][m] = av.w;
        }
        {
            int kk = tid >> 4, c4 = (tid & 15) * 4;
            *(float4*)&Bs[kk][c4] =
                *(const float4*)(Vh + (size_t)(kc + kk) * PDH + c4);
        }
        __syncthreads();
#pragma unroll
        for (int kk = 0; kk < 16; kk++) {
            ulonglong2 aa0 = *(const ulonglong2*)&As[kk][ty * 8];
            ulonglong2 aa1 = *(const ulonglong2*)&As[kk][ty * 8 + 4];
            u64 a2[4] = {aa0.x, aa0.y, aa1.x, aa1.y};
            float4 b4 = *(const float4*)&Bs[kk][tx * 4];
            u64 b2[4] = {dup2(b4.x), dup2(b4.y), dup2(b4.z), dup2(b4.w)};
#pragma unroll
            for (int i2 = 0; i2 < 4; i2++)
#pragma unroll
                for (int j = 0; j < 4; j++) ffma2(acc[i2][j], a2[i2], b2[j]);
        }
        __syncthreads();
    }

#pragma unroll
    for (int i2 = 0; i2 < 4; i2++) {
        float lo[4], hi[4];
#pragma unroll
        for (int j = 0; j < 4; j++) unpack2(acc[i2][j], lo[j], hi[j]);
        int s0 = m0 + ty * 8 + 2 * i2;
        *(float4*)(g_ctx + (size_t)(b_ * PS + s0) * PD + h_ * PDH + tx * 4) =
            *(float4*)&lo[0];
        *(float4*)(g_ctx + (size_t)(b_ * PS + s0 + 1) * PD + h_ * PDH + tx * 4) =
            *(float4*)&hi[0];
    }
}

// ---------------------------------------------------------------------------
// Kernel 5: out = ctx @ Wo + bo (packed f32x2 math).
// ---------------------------------------------------------------------------
__global__ __launch_bounds__(256) void out_proj_kernel(
    const float* __restrict__ Wo, const float* __restrict__ bo,
    float* __restrict__ out)
{
    __shared__ float As[16][132];
    __shared__ float Bs[16][128];

    const int m0 = blockIdx.x * 128;
    const int n0 = blockIdx.y * 128;
    const int tid = threadIdx.x;
    const int tx = tid & 15, ty = tid >> 4;

    u64 acc[8][4];
#pragma unroll
    for (int i = 0; i < 8; i++)
#pragma unroll
        for (int j2 = 0; j2 < 4; j2++) acc[i][j2] = 0ull;

    for (int d0 = 0; d0 < PD; d0 += 16) {
#pragma unroll
        for (int l = 0; l < 2; l++) {
            int f = tid + 256 * l;
            int m = f >> 2, c4 = (f & 3) * 4;
            float4 av = *(const float4*)(g_ctx + (size_t)(m0 + m) * PD + d0 + c4);
            As[c4 + 0][m] = av.x; As[c4 + 1][m] = av.y;
            As[c4 + 2][m] = av.z; As[c4 + 3][m] = av.w;
        }
#pragma unroll
        for (int l = 0; l < 2; l++) {
            int f = tid + 256 * l;
            int kk = f >> 5, c4 = (f & 31) * 4;
            *(float4*)&Bs[kk][c4] =
                *(const float4*)(Wo + (size_t)(d0 + kk) * PD + n0 + c4);
        }
        __syncthreads();
#pragma unroll
        for (int kk = 0; kk < 16; kk++) {
            float a[8];
            *(float4*)&a[0] = *(const float4*)&As[kk][ty * 8];
            *(float4*)&a[4] = *(const float4*)&As[kk][ty * 8 + 4];
            ulonglong2 bb0 = *(const ulonglong2*)&Bs[kk][tx * 8];
            ulonglong2 bb1 = *(const ulonglong2*)&Bs[kk][tx * 8 + 4];
            u64 b2[4] = {bb0.x, bb0.y, bb1.x, bb1.y};
            u64 a2[8];
#pragma unroll
            for (int i = 0; i < 8; i++) a2[i] = dup2(a[i]);
#pragma unroll
            for (int i = 0; i < 8; i++)
#pragma unroll
                for (int j2 = 0; j2 < 4; j2++) ffma2(acc[i][j2], a2[i], b2[j2]);
        }
        __syncthreads();
    }

    float bcol[8];
#pragma unroll
    for (int j = 0; j < 8; j++) bcol[j] = bo[n0 + tx * 8 + j];

#pragma unroll
    for (int i = 0; i < 8; i++) {
        int r = m0 + ty * 8 + i;
        float* dst = out + (size_t)r * PD + n0 + tx * 8;
        float o[8];
#pragma unroll
        for (int j2 = 0; j2 < 4; j2++) unpack2(acc[i][j2], o[2 * j2], o[2 * j2 + 1]);
#pragma unroll
        for (int j = 0; j < 8; j++) o[j] += bcol[j];
        *(float4*)dst       = *(float4*)&o[0];
        *(float4*)(dst + 4) = *(float4*)&o[4];
    }
}

// ---------------------------------------------------------------------------
extern "C" void kernel_launch(void* const* d_in, const int* in_sizes, int n_in,
                              void* d_out, int out_size)
{
    (void)in_sizes; (void)n_in; (void)out_size;
    const float* q  = (const float*)d_in[0];
    const float* k  = (const float*)d_in[1];
    const float* v  = (const float*)d_in[2];
    const float* Wq = (const float*)d_in[3];
    const float* Wk = (const float*)d_in[4];
    const float* Wv = (const float*)d_in[5];
    const float* bq = (const float*)d_in[6];
    const float* bk = (const float*)d_in[7];
    const float* bv = (const float*)d_in[8];
    const float* Wo = (const float*)d_in[9];
    const float* bo = (const float*)d_in[10];

    float* out = (float*)d_out;
    float* aw  = out + OUT_ELEMS;    // aws [H][B][S][S] follows out [B][S][D]

    qkv_proj_kernel<<<dim3(PBS / 128, PD / 128, 3), 256>>>(
        q, k, v, Wq, Wk, Wv, bq, bk, bv);
    scores_kernel<<<dim3(PS / 128, PS / 128, PB * PH), 256>>>(aw);
    softmax_kernel<<<PB * PH * PS, 256>>>(aw);
    ctx_kernel<<<dim3(PS / 128, 1, PB * PH), 256>>>(aw);
    out_proj_kernel<<<dim3(PBS / 128, PD / 128), 256>>>(Wo, bo, out);
}

// round 14
// speedup vs baseline: 1.0622x; 1.0622x over previous
#include <cuda_runtime.h>

// Problem constants
#define PB 2
#define PS 2048
#define PD 1024
#define PH 16
#define PDH 64
#define PBS (PB * PS)                        // 4096 rows
#define OUT_ELEMS ((long long)PB * PS * PD)  // 4194304

typedef unsigned long long u64;

// ---- packed fp32x2 helpers (Blackwell FFMA2 path) -------------------------
__device__ __forceinline__ u64 dup2(float x) {
    u64 r;
    asm("mov.b64 %0, {%1, %1};" : "=l"(r) : "f"(x));
    return r;
}
__device__ __forceinline__ void unpack2(u64 p, float& lo, float& hi) {
    asm("mov.b64 {%0, %1}, %2;" : "=f"(lo), "=f"(hi) : "l"(p));
}
__device__ __forceinline__ void ffma2(u64& d, u64 a, u64 b) {
    asm("fma.rn.f32x2 %0, %1, %2, %0;" : "+l"(d) : "l"(a), "l"(b));
}

// Scratch (device globals; no allocation allowed)
__device__ float g_Q[(size_t)PB * PH * PS * PDH];   // [b][h][s][k]
__device__ float g_K[(size_t)PB * PH * PS * PDH];
__device__ float g_V[(size_t)PB * PH * PS * PDH];
__device__ float g_ctx[(size_t)PB * PS * PD];       // [b][s][h*64+k]

// ---------------------------------------------------------------------------
// Kernel 1: fused Q/K/V per-head projections. Double-buffered smem pipeline.
// ---------------------------------------------------------------------------
__global__ __launch_bounds__(256) void qkv_proj_kernel(
    const float* __restrict__ q, const float* __restrict__ k,
    const float* __restrict__ v, const float* __restrict__ Wq,
    const float* __restrict__ Wk, const float* __restrict__ Wv,
    const float* __restrict__ bq, const float* __restrict__ bk,
    const float* __restrict__ bv)
{
    __shared__ float As[2][16][132];   // transposed: As[buf][kk][m]
    __shared__ float Bs[2][16][128];   // Bs[buf][kk][j]

    const int zz = blockIdx.z;
    const float* A    = (zz == 0) ? q  : (zz == 1) ? k  : v;
    const float* W    = (zz == 0) ? Wq : (zz == 1) ? Wk : Wv;
    const float* bias = (zz == 0) ? bq : (zz == 1) ? bk : bv;
    float* outp       = (zz == 0) ? g_Q : (zz == 1) ? g_K : g_V;
    const float scale = (zz == 0) ? 0.125f : 1.0f;   // 1/sqrt(DH) folded into Q

    const int m0 = blockIdx.x * 128;
    const int h0 = blockIdx.y * 2;
    const int tid = threadIdx.x;
    const int tx = tid & 15;
    const int ty = tid >> 4;

    // per-thread load coordinates (constant over K loop)
    int am[2], ac4[2], bkk[2], bc4[2], bhh[2], bkc[2];
#pragma unroll
    for (int l = 0; l < 2; l++) {
        int f = tid + 256 * l;
        am[l] = f >> 2;  ac4[l] = (f & 3) * 4;
        bkk[l] = f >> 5; bc4[l] = (f & 31) * 4;
        bhh[l] = h0 + (bc4[l] >> 6);
        bkc[l] = bc4[l] & 63;
    }

    u64 acc[8][4];
#pragma unroll
    for (int i = 0; i < 8; i++)
#pragma unroll
        for (int j2 = 0; j2 < 4; j2++) acc[i][j2] = 0ull;

    float4 pa[2], pb[2];
    // prologue: load tile 0
#pragma unroll
    for (int l = 0; l < 2; l++) {
        pa[l] = *(const float4*)(A + (size_t)(m0 + am[l]) * PD + ac4[l]);
        pb[l] = *(const float4*)(W + ((size_t)bhh[l] * PD + bkk[l]) * PDH + bkc[l]);
    }
#pragma unroll
    for (int l = 0; l < 2; l++) {
        As[0][ac4[l] + 0][am[l]] = pa[l].x; As[0][ac4[l] + 1][am[l]] = pa[l].y;
        As[0][ac4[l] + 2][am[l]] = pa[l].z; As[0][ac4[l] + 3][am[l]] = pa[l].w;
        *(float4*)&Bs[0][bkk[l]][bc4[l]] = pb[l];
    }
    __syncthreads();

    const int NIT = PD / 16;
    for (int it = 0; it < NIT; it++) {
        const int cur = it & 1;
        const bool hn = (it + 1 < NIT);
        if (hn) {
            int d0 = (it + 1) * 16;
#pragma unroll
            for (int l = 0; l < 2; l++) {
                pa[l] = *(const float4*)(A + (size_t)(m0 + am[l]) * PD + d0 + ac4[l]);
                pb[l] = *(const float4*)(W + ((size_t)bhh[l] * PD + d0 + bkk[l]) * PDH + bkc[l]);
            }
        }
#pragma unroll
        for (int kk = 0; kk < 16; kk++) {
            float a[8];
            *(float4*)&a[0] = *(const float4*)&As[cur][kk][ty * 8];
            *(float4*)&a[4] = *(const float4*)&As[cur][kk][ty * 8 + 4];
            ulonglong2 bb0 = *(const ulonglong2*)&Bs[cur][kk][tx * 8];
            ulonglong2 bb1 = *(const ulonglong2*)&Bs[cur][kk][tx * 8 + 4];
            u64 b2[4] = {bb0.x, bb0.y, bb1.x, bb1.y};
            u64 a2[8];
#pragma unroll
            for (int i = 0; i < 8; i++) a2[i] = dup2(a[i]);
#pragma unroll
            for (int i = 0; i < 8; i++)
#pragma unroll
                for (int j2 = 0; j2 < 4; j2++) ffma2(acc[i][j2], a2[i], b2[j2]);
        }
        if (hn) {
            const int nxt = cur ^ 1;
#pragma unroll
            for (int l = 0; l < 2; l++) {
                As[nxt][ac4[l] + 0][am[l]] = pa[l].x; As[nxt][ac4[l] + 1][am[l]] = pa[l].y;
                As[nxt][ac4[l] + 2][am[l]] = pa[l].z; As[nxt][ac4[l] + 3][am[l]] = pa[l].w;
                *(float4*)&Bs[nxt][bkk[l]][bc4[l]] = pb[l];
            }
        }
        __syncthreads();
    }

    const int jbase = tx * 8;
    const int hh = h0 + (jbase >> 6);
    const int kc0 = jbase & 63;
    float bcol[8];
#pragma unroll
    for (int j = 0; j < 8; j++) bcol[j] = bias[hh * PDH + kc0 + j];

#pragma unroll
    for (int i = 0; i < 8; i++) {
        int r = m0 + ty * 8 + i;
        int bb_ = r >> 11;
        int s = r & (PS - 1);
        float* dst = outp + ((size_t)(bb_ * PH + hh) * PS + s) * PDH + kc0;
        float o[8];
#pragma unroll
        for (int j2 = 0; j2 < 4; j2++) unpack2(acc[i][j2], o[2 * j2], o[2 * j2 + 1]);
#pragma unroll
        for (int j = 0; j < 8; j++) o[j] = (o[j] + bcol[j]) * scale;
        *(float4*)dst       = *(float4*)&o[0];
        *(float4*)(dst + 4) = *(float4*)&o[4];
    }
}

// ---------------------------------------------------------------------------
// Kernel 2: raw scores = Qh * Kh^T into aws[h][b][:, :]. Double-buffered.
// ---------------------------------------------------------------------------
__global__ __launch_bounds__(256) void scores_kernel(float* __restrict__ aw)
{
    __shared__ float As[2][16][132];
    __shared__ float Bs[2][16][132];

    const int zz = blockIdx.z;           // b*H + h
    const int b_ = zz >> 4, h_ = zz & 15;
    const float* Qh = g_Q + (size_t)zz * PS * PDH;
    const float* Kh = g_K + (size_t)zz * PS * PDH;
    float* awb = aw + (size_t)(h_ * PB + b_) * PS * PS;

    const int m0 = blockIdx.x * 128;
    const int n0 = blockIdx.y * 128;
    const int tid = threadIdx.x;
    const int tx = tid & 15, ty = tid >> 4;

    int am[2], ac4[2];
#pragma unroll
    for (int l = 0; l < 2; l++) {
        int f = tid + 256 * l;
        am[l] = f >> 2; ac4[l] = (f & 3) * 4;
    }

    u64 acc[8][4];
#pragma unroll
    for (int i = 0; i < 8; i++)
#pragma unroll
        for (int j2 = 0; j2 < 4; j2++) acc[i][j2] = 0ull;

    float4 pq[2], pk[2];
#pragma unroll
    for (int l = 0; l < 2; l++) {
        pq[l] = *(const float4*)(Qh + (size_t)(m0 + am[l]) * PDH + ac4[l]);
        pk[l] = *(const float4*)(Kh + (size_t)(n0 + am[l]) * PDH + ac4[l]);
    }
#pragma unroll
    for (int l = 0; l < 2; l++) {
        As[0][ac4[l] + 0][am[l]] = pq[l].x; As[0][ac4[l] + 1][am[l]] = pq[l].y;
        As[0][ac4[l] + 2][am[l]] = pq[l].z; As[0][ac4[l] + 3][am[l]] = pq[l].w;
        Bs[0][ac4[l] + 0][am[l]] = pk[l].x; Bs[0][ac4[l] + 1][am[l]] = pk[l].y;
        Bs[0][ac4[l] + 2][am[l]] = pk[l].z; Bs[0][ac4[l] + 3][am[l]] = pk[l].w;
    }
    __syncthreads();

    const int NIT = PDH / 16;            // 4
    for (int it = 0; it < NIT; it++) {
        const int cur = it & 1;
        const bool hn = (it + 1 < NIT);
        if (hn) {
            int d0 = (it + 1) * 16;
#pragma unroll
            for (int l = 0; l < 2; l++) {
                pq[l] = *(const float4*)(Qh + (size_t)(m0 + am[l]) * PDH + d0 + ac4[l]);
                pk[l] = *(const float4*)(Kh + (size_t)(n0 + am[l]) * PDH + d0 + ac4[l]);
            }
        }
#pragma unroll
        for (int kk = 0; kk < 16; kk++) {
            float a[8];
            *(float4*)&a[0] = *(const float4*)&As[cur][kk][ty * 8];
            *(float4*)&a[4] = *(const float4*)&As[cur][kk][ty * 8 + 4];
            ulonglong2 bb0 = *(const ulonglong2*)&Bs[cur][kk][tx * 8];
            ulonglong2 bb1 = *(const ulonglong2*)&Bs[cur][kk][tx * 8 + 4];
            u64 b2[4] = {bb0.x, bb0.y, bb1.x, bb1.y};
            u64 a2[8];
#pragma unroll
            for (int i = 0; i < 8; i++) a2[i] = dup2(a[i]);
#pragma unroll
            for (int i = 0; i < 8; i++)
#pragma unroll
                for (int j2 = 0; j2 < 4; j2++) ffma2(acc[i][j2], a2[i], b2[j2]);
        }
        if (hn) {
            const int nxt = cur ^ 1;
#pragma unroll
            for (int l = 0; l < 2; l++) {
                As[nxt][ac4[l] + 0][am[l]] = pq[l].x; As[nxt][ac4[l] + 1][am[l]] = pq[l].y;
                As[nxt][ac4[l] + 2][am[l]] = pq[l].z; As[nxt][ac4[l] + 3][am[l]] = pq[l].w;
                Bs[nxt][ac4[l] + 0][am[l]] = pk[l].x; Bs[nxt][ac4[l] + 1][am[l]] = pk[l].y;
                Bs[nxt][ac4[l] + 2][am[l]] = pk[l].z; Bs[nxt][ac4[l] + 3][am[l]] = pk[l].w;
            }
        }
        __syncthreads();
    }

#pragma unroll
    for (int i = 0; i < 8; i++) {
        int qi = m0 + ty * 8 + i;
        float* dst = awb + (size_t)qi * PS + n0 + tx * 8;
        float o[8];
#pragma unroll
        for (int j2 = 0; j2 < 4; j2++) unpack2(acc[i][j2], o[2 * j2], o[2 * j2 + 1]);
        *(float4*)dst       = *(float4*)&o[0];
        *(float4*)(dst + 4) = *(float4*)&o[4];
    }
}

// ---------------------------------------------------------------------------
// Kernel 3: in-place row softmax over aws (memory bound; unchanged).
// ---------------------------------------------------------------------------
__global__ __launch_bounds__(256) void softmax_kernel(float* __restrict__ aw)
{
    float* p = aw + (size_t)blockIdx.x * PS;
    const int t = threadIdx.x;
    const int lane = t & 31, warp = t >> 5;

    float x[8];
    *(float4*)&x[0] = ((const float4*)p)[t];
    *(float4*)&x[4] = ((const float4*)p)[t + 256];

    float m = x[0];
#pragma unroll
    for (int i = 1; i < 8; i++) m = fmaxf(m, x[i]);
#pragma unroll
    for (int o = 16; o > 0; o >>= 1) m = fmaxf(m, __shfl_xor_sync(0xffffffffu, m, o));

    __shared__ float red[8];
    if (lane == 0) red[warp] = m;
    __syncthreads();
    float mm = red[0];
#pragma unroll
    for (int i = 1; i < 8; i++) mm = fmaxf(mm, red[i]);

    float ssum = 0.f;
#pragma unroll
    for (int i = 0; i < 8; i++) { x[i] = __expf(x[i] - mm); ssum += x[i]; }
#pragma unroll
    for (int o = 16; o > 0; o >>= 1) ssum += __shfl_xor_sync(0xffffffffu, ssum, o);

    __syncthreads();
    if (lane == 0) red[warp] = ssum;
    __syncthreads();
    float tot = 0.f;
#pragma unroll
    for (int i = 0; i < 8; i++) tot += red[i];
    float inv = 1.0f / tot;
#pragma unroll
    for (int i = 0; i < 8; i++) x[i] *= inv;

    ((float4*)p)[t]       = *(float4*)&x[0];
    ((float4*)p)[t + 256] = *(float4*)&x[4];
}

// ---------------------------------------------------------------------------
// Kernel 4: ctx = aw * V per (b,h). Double-buffered; f32x2 packed over rows.
// ---------------------------------------------------------------------------
__global__ __launch_bounds__(256) void ctx_kernel(const float* __restrict__ aw)
{
    __shared__ float As[2][16][132];   // transposed aw tile: As[buf][kk][m]
    __shared__ float Bs[2][16][64];    // V tile, natural layout

    const int zz = blockIdx.z;
    const int b_ = zz >> 4, h_ = zz & 15;
    const float* awb = aw + (size_t)(h_ * PB + b_) * PS * PS;
    const float* Vh = g_V + (size_t)zz * PS * PDH;

    const int m0 = blockIdx.x * 128;
    const int tid = threadIdx.x;
    const int tx = tid & 15, ty = tid >> 4;

    int am[2], ac4[2];
#pragma unroll
    for (int l = 0; l < 2; l++) {
        int f = tid + 256 * l;
        am[l] = f >> 2; ac4[l] = (f & 3) * 4;
    }
    const int vkk = tid >> 4, vc4 = (tid & 15) * 4;

    u64 acc[4][4];                  // [i2][j]: lo=row 2*i2, hi=row 2*i2+1
#pragma unroll
    for (int i2 = 0; i2 < 4; i2++)
#pragma unroll
        for (int j = 0; j < 4; j++) acc[i2][j] = 0ull;

    float4 pa[2], pv;
#pragma unroll
    for (int l = 0; l < 2; l++)
        pa[l] = *(const float4*)(awb + (size_t)(m0 + am[l]) * PS + ac4[l]);
    pv = *(const float4*)(Vh + (size_t)vkk * PDH + vc4);
#pragma unroll
    for (int l = 0; l < 2; l++) {
        As[0][ac4[l] + 0][am[l]] = pa[l].x; As[0][ac4[l] + 1][am[l]] = pa[l].y;
        As[0][ac4[l] + 2][am[l]] = pa[l].z; As[0][ac4[l] + 3][am[l]] = pa[l].w;
    }
    *(float4*)&Bs[0][vkk][vc4] = pv;
    __syncthreads();

    const int NIT = PS / 16;          // 128
    for (int it = 0; it < NIT; it++) {
        const int cur = it & 1;
        const bool hn = (it + 1 < NIT);
        if (hn) {
            int kc = (it + 1) * 16;
#pragma unroll
            for (int l = 0; l < 2; l++)
                pa[l] = *(const float4*)(awb + (size_t)(m0 + am[l]) * PS + kc + ac4[l]);
            pv = *(const float4*)(Vh + (size_t)(kc + vkk) * PDH + vc4);
        }
#pragma unroll
        for (int kk = 0; kk < 16; kk++) {
            ulonglong2 aa0 = *(const ulonglong2*)&As[cur][kk][ty * 8];
            ulonglong2 aa1 = *(const ulonglong2*)&As[cur][kk][ty * 8 + 4];
            u64 a2[4] = {aa0.x, aa0.y, aa1.x, aa1.y};
            float4 b4 = *(const float4*)&Bs[cur][kk][tx * 4];
            u64 b2[4] = {dup2(b4.x), dup2(b4.y), dup2(b4.z), dup2(b4.w)};
#pragma unroll
            for (int i2 = 0; i2 < 4; i2++)
#pragma unroll
                for (int j = 0; j < 4; j++) ffma2(acc[i2][j], a2[i2], b2[j]);
        }
        if (hn) {
            const int nxt = cur ^ 1;
#pragma unroll
            for (int l = 0; l < 2; l++) {
                As[nxt][ac4[l] + 0][am[l]] = pa[l].x; As[nxt][ac4[l] + 1][am[l]] = pa[l].y;
                As[nxt][ac4[l] + 2][am[l]] = pa[l].z; As[nxt][ac4[l] + 3][am[l]] = pa[l].w;
            }
            *(float4*)&Bs[nxt][vkk][vc4] = pv;
        }
        __syncthreads();
    }

#pragma unroll
    for (int i2 = 0; i2 < 4; i2++) {
        float lo[4], hi[4];
#pragma unroll
        for (int j = 0; j < 4; j++) unpack2(acc[i2][j], lo[j], hi[j]);
        int s0 = m0 + ty * 8 + 2 * i2;
        *(float4*)(g_ctx + (size_t)(b_ * PS + s0) * PD + h_ * PDH + tx * 4) =
            *(float4*)&lo[0];
        *(float4*)(g_ctx + (size_t)(b_ * PS + s0 + 1) * PD + h_ * PDH + tx * 4) =
            *(float4*)&hi[0];
    }
}

// ---------------------------------------------------------------------------
// Kernel 5: out = ctx @ Wo + bo. Double-buffered.
// ---------------------------------------------------------------------------
__global__ __launch_bounds__(256) void out_proj_kernel(
    const float* __restrict__ Wo, const float* __restrict__ bo,
    float* __restrict__ out)
{
    __shared__ float As[2][16][132];
    __shared__ float Bs[2][16][128];

    const int m0 = blockIdx.x * 128;
    const int n0 = blockIdx.y * 128;
    const int tid = threadIdx.x;
    const int tx = tid & 15, ty = tid >> 4;

    int am[2], ac4[2], bkk[2], bc4[2];
#pragma unroll
    for (int l = 0; l < 2; l++) {
        int f = tid + 256 * l;
        am[l] = f >> 2;  ac4[l] = (f & 3) * 4;
        bkk[l] = f >> 5; bc4[l] = (f & 31) * 4;
    }

    u64 acc[8][4];
#pragma unroll
    for (int i = 0; i < 8; i++)
#pragma unroll
        for (int j2 = 0; j2 < 4; j2++) acc[i][j2] = 0ull;

    float4 pa[2], pb[2];
#pragma unroll
    for (int l = 0; l < 2; l++) {
        pa[l] = *(const float4*)(g_ctx + (size_t)(m0 + am[l]) * PD + ac4[l]);
        pb[l] = *(const float4*)(Wo + (size_t)bkk[l] * PD + n0 + bc4[l]);
    }
#pragma unroll
    for (int l = 0; l < 2; l++) {
        As[0][ac4[l] + 0][am[l]] = pa[l].x; As[0][ac4[l] + 1][am[l]] = pa[l].y;
        As[0][ac4[l] + 2][am[l]] = pa[l].z; As[0][ac4[l] + 3][am[l]] = pa[l].w;
        *(float4*)&Bs[0][bkk[l]][bc4[l]] = pb[l];
    }
    __syncthreads();

    const int NIT = PD / 16;
    for (int it = 0; it < NIT; it++) {
        const int cur = it & 1;
        const bool hn = (it + 1 < NIT);
        if (hn) {
            int d0 = (it + 1) * 16;
#pragma unroll
            for (int l = 0; l < 2; l++) {
                pa[l] = *(const float4*)(g_ctx + (size_t)(m0 + am[l]) * PD + d0 + ac4[l]);
                pb[l] = *(const float4*)(Wo + (size_t)(d0 + bkk[l]) * PD + n0 + bc4[l]);
            }
        }
#pragma unroll
        for (int kk = 0; kk < 16; kk++) {
            float a[8];
            *(float4*)&a[0] = *(const float4*)&As[cur][kk][ty * 8];
            *(float4*)&a[4] = *(const float4*)&As[cur][kk][ty * 8 + 4];
            ulonglong2 bb0 = *(const ulonglong2*)&Bs[cur][kk][tx * 8];
            ulonglong2 bb1 = *(const ulonglong2*)&Bs[cur][kk][tx * 8 + 4];
            u64 b2[4] = {bb0.x, bb0.y, bb1.x, bb1.y};
            u64 a2[8];
#pragma unroll
            for (int i = 0; i < 8; i++) a2[i] = dup2(a[i]);
#pragma unroll
            for (int i = 0; i < 8; i++)
#pragma unroll
                for (int j2 = 0; j2 < 4; j2++) ffma2(acc[i][j2], a2[i], b2[j2]);
        }
        if (hn) {
            const int nxt = cur ^ 1;
#pragma unroll
            for (int l = 0; l < 2; l++) {
                As[nxt][ac4[l] + 0][am[l]] = pa[l].x; As[nxt][ac4[l] + 1][am[l]] = pa[l].y;
                As[nxt][ac4[l] + 2][am[l]] = pa[l].z; As[nxt][ac4[l] + 3][am[l]] = pa[l].w;
                *(float4*)&Bs[nxt][bkk[l]][bc4[l]] = pb[l];
            }
        }
        __syncthreads();
    }

    float bcol[8];
#pragma unroll
    for (int j = 0; j < 8; j++) bcol[j] = bo[n0 + tx * 8 + j];

#pragma unroll
    for (int i = 0; i < 8; i++) {
        int r = m0 + ty * 8 + i;
        float* dst = out + (size_t)r * PD + n0 + tx * 8;
        float o[8];
#pragma unroll
        for (int j2 = 0; j2 < 4; j2++) unpack2(acc[i][j2], o[2 * j2], o[2 * j2 + 1]);
#pragma unroll
        for (int j = 0; j < 8; j++) o[j] += bcol[j];
        *(float4*)dst       = *(float4*)&o[0];
        *(float4*)(dst + 4) = *(float4*)&o[4];
    }
}

// ---------------------------------------------------------------------------
extern "C" void kernel_launch(void* const* d_in, const int* in_sizes, int n_in,
                              void* d_out, int out_size)
{
    (void)in_sizes; (void)n_in; (void)out_size;
    const float* q  = (const float*)d_in[0];
    const float* k  = (const float*)d_in[1];
    const float* v  = (const float*)d_in[2];
    const float* Wq = (const float*)d_in[3];
    const float* Wk = (const float*)d_in[4];
    const float* Wv = (const float*)d_in[5];
    const float* bq = (const float*)d_in[6];
    const float* bk = (const float*)d_in[7];
    const float* bv = (const float*)d_in[8];
    const float* Wo = (const float*)d_in[9];
    const float* bo = (const float*)d_in[10];

    float* out = (float*)d_out;
    float* aw  = out + OUT_ELEMS;    // aws [H][B][S][S] follows out [B][S][D]

    qkv_proj_kernel<<<dim3(PBS / 128, PD / 128, 3), 256>>>(
        q, k, v, Wq, Wk, Wv, bq, bk, bv);
    scores_kernel<<<dim3(PS / 128, PS / 128, PB * PH), 256>>>(aw);
    softmax_kernel<<<PB * PH * PS, 256>>>(aw);
    ctx_kernel<<<dim3(PS / 128, 1, PB * PH), 256>>>(aw);
    out_proj_kernel<<<dim3(PBS / 128, PD / 128), 256>>>(Wo, bo, out);  // PD/128 = 8 N-tiles
}

// round 15
// speedup vs baseline: 1.0962x; 1.0321x over previous
#include <cuda_runtime.h>

// Problem constants
#define PB 2
#define PS 2048
#define PD 1024
#define PH 16
#define PDH 64
#define PBS (PB * PS)                        // 4096 rows
#define OUT_ELEMS ((long long)PB * PS * PD)  // 4194304

typedef unsigned long long u64;

// ---- packed fp32x2 helpers (Blackwell FFMA2 path) -------------------------
__device__ __forceinline__ u64 dup2(float x) {
    u64 r;
    asm("mov.b64 %0, {%1, %1};" : "=l"(r) : "f"(x));
    return r;
}
__device__ __forceinline__ void unpack2(u64 p, float& lo, float& hi) {
    asm("mov.b64 {%0, %1}, %2;" : "=f"(lo), "=f"(hi) : "l"(p));
}
__device__ __forceinline__ void ffma2(u64& d, u64 a, u64 b) {
    asm("fma.rn.f32x2 %0, %1, %2, %0;" : "+l"(d) : "l"(a), "l"(b));
}

// Scratch (device globals; no allocation allowed)
__device__ float g_Q[(size_t)PB * PH * PS * PDH];   // [b][h][s][k]
__device__ float g_K[(size_t)PB * PH * PS * PDH];
__device__ float g_V[(size_t)PB * PH * PS * PDH];
__device__ float g_ctx[(size_t)PB * PS * PD];       // [b][s][h*64+k]

// ---------------------------------------------------------------------------
// Kernel 1: fused Q/K/V per-head projections. Double-buffered smem pipeline.
// ---------------------------------------------------------------------------
__global__ __launch_bounds__(256) void qkv_proj_kernel(
    const float* __restrict__ q, const float* __restrict__ k,
    const float* __restrict__ v, const float* __restrict__ Wq,
    const float* __restrict__ Wk, const float* __restrict__ Wv,
    const float* __restrict__ bq, const float* __restrict__ bk,
    const float* __restrict__ bv)
{
    __shared__ float As[2][16][132];   // transposed: As[buf][kk][m]
    __shared__ float Bs[2][16][128];   // Bs[buf][kk][j]

    const int zz = blockIdx.z;
    const float* A    = (zz == 0) ? q  : (zz == 1) ? k  : v;
    const float* W    = (zz == 0) ? Wq : (zz == 1) ? Wk : Wv;
    const float* bias = (zz == 0) ? bq : (zz == 1) ? bk : bv;
    float* outp       = (zz == 0) ? g_Q : (zz == 1) ? g_K : g_V;
    const float scale = (zz == 0) ? 0.125f : 1.0f;   // 1/sqrt(DH) folded into Q

    const int m0 = blockIdx.x * 128;
    const int h0 = blockIdx.y * 2;
    const int tid = threadIdx.x;
    const int tx = tid & 15;
    const int ty = tid >> 4;

    // per-thread load coordinates (constant over K loop)
    int am[2], ac4[2], bkk[2], bc4[2], bhh[2], bkc[2];
#pragma unroll
    for (int l = 0; l < 2; l++) {
        int f = tid + 256 * l;
        am[l] = f >> 2;  ac4[l] = (f & 3) * 4;
        bkk[l] = f >> 5; bc4[l] = (f & 31) * 4;
        bhh[l] = h0 + (bc4[l] >> 6);
        bkc[l] = bc4[l] & 63;
    }

    u64 acc[8][4];
#pragma unroll
    for (int i = 0; i < 8; i++)
#pragma unroll
        for (int j2 = 0; j2 < 4; j2++) acc[i][j2] = 0ull;

    float4 pa[2], pb[2];
    // prologue: load tile 0
#pragma unroll
    for (int l = 0; l < 2; l++) {
        pa[l] = *(const float4*)(A + (size_t)(m0 + am[l]) * PD + ac4[l]);
        pb[l] = *(const float4*)(W + ((size_t)bhh[l] * PD + bkk[l]) * PDH + bkc[l]);
    }
#pragma unroll
    for (int l = 0; l < 2; l++) {
        As[0][ac4[l] + 0][am[l]] = pa[l].x; As[0][ac4[l] + 1][am[l]] = pa[l].y;
        As[0][ac4[l] + 2][am[l]] = pa[l].z; As[0][ac4[l] + 3][am[l]] = pa[l].w;
        *(float4*)&Bs[0][bkk[l]][bc4[l]] = pb[l];
    }
    __syncthreads();

    const int NIT = PD / 16;
    for (int it = 0; it < NIT; it++) {
        const int cur = it & 1;
        const bool hn = (it + 1 < NIT);
        if (hn) {
            int d0 = (it + 1) * 16;
#pragma unroll
            for (int l = 0; l < 2; l++) {
                pa[l] = *(const float4*)(A + (size_t)(m0 + am[l]) * PD + d0 + ac4[l]);
                pb[l] = *(const float4*)(W + ((size_t)bhh[l] * PD + d0 + bkk[l]) * PDH + bkc[l]);
            }
        }
#pragma unroll
        for (int kk = 0; kk < 16; kk++) {
            float a[8];
            *(float4*)&a[0] = *(const float4*)&As[cur][kk][ty * 8];
            *(float4*)&a[4] = *(const float4*)&As[cur][kk][ty * 8 + 4];
            ulonglong2 bb0 = *(const ulonglong2*)&Bs[cur][kk][tx * 8];
            ulonglong2 bb1 = *(const ulonglong2*)&Bs[cur][kk][tx * 8 + 4];
            u64 b2[4] = {bb0.x, bb0.y, bb1.x, bb1.y};
            u64 a2[8];
#pragma unroll
            for (int i = 0; i < 8; i++) a2[i] = dup2(a[i]);
#pragma unroll
            for (int i = 0; i < 8; i++)
#pragma unroll
                for (int j2 = 0; j2 < 4; j2++) ffma2(acc[i][j2], a2[i], b2[j2]);
        }
        if (hn) {
            const int nxt = cur ^ 1;
#pragma unroll
            for (int l = 0; l < 2; l++) {
                As[nxt][ac4[l] + 0][am[l]] = pa[l].x; As[nxt][ac4[l] + 1][am[l]] = pa[l].y;
                As[nxt][ac4[l] + 2][am[l]] = pa[l].z; As[nxt][ac4[l] + 3][am[l]] = pa[l].w;
                *(float4*)&Bs[nxt][bkk[l]][bc4[l]] = pb[l];
            }
        }
        __syncthreads();
    }

    const int jbase = tx * 8;
    const int hh = h0 + (jbase >> 6);
    const int kc0 = jbase & 63;
    float bcol[8];
#pragma unroll
    for (int j = 0; j < 8; j++) bcol[j] = bias[hh * PDH + kc0 + j];

#pragma unroll
    for (int i = 0; i < 8; i++) {
        int r = m0 + ty * 8 + i;
        int bb_ = r >> 11;
        int s = r & (PS - 1);
        float* dst = outp + ((size_t)(bb_ * PH + hh) * PS + s) * PDH + kc0;
        float o[8];
#pragma unroll
        for (int j2 = 0; j2 < 4; j2++) unpack2(acc[i][j2], o[2 * j2], o[2 * j2 + 1]);
#pragma unroll
        for (int j = 0; j < 8; j++) o[j] = (o[j] + bcol[j]) * scale;
        *(float4*)dst       = *(float4*)&o[0];
        *(float4*)(dst + 4) = *(float4*)&o[4];
    }
}

// ---------------------------------------------------------------------------
// Kernel 2: raw scores = Qh * Kh^T into aws[h][b][:, :]. Double-buffered.
// ---------------------------------------------------------------------------
__global__ __launch_bounds__(256) void scores_kernel(float* __restrict__ aw)
{
    __shared__ float As[2][16][132];
    __shared__ float Bs[2][16][132];

    const int zz = blockIdx.z;           // b*H + h
    const int b_ = zz >> 4, h_ = zz & 15;
    const float* Qh = g_Q + (size_t)zz * PS * PDH;
    const float* Kh = g_K + (size_t)zz * PS * PDH;
    float* awb = aw + (size_t)(h_ * PB + b_) * PS * PS;

    const int m0 = blockIdx.x * 128;
    const int n0 = blockIdx.y * 128;
    const int tid = threadIdx.x;
    const int tx = tid & 15, ty = tid >> 4;

    int am[2], ac4[2];
#pragma unroll
    for (int l = 0; l < 2; l++) {
        int f = tid + 256 * l;
        am[l] = f >> 2; ac4[l] = (f & 3) * 4;
    }

    u64 acc[8][4];
#pragma unroll
    for (int i = 0; i < 8; i++)
#pragma unroll
        for (int j2 = 0; j2 < 4; j2++) acc[i][j2] = 0ull;

    float4 pq[2], pk[2];
#pragma unroll
    for (int l = 0; l < 2; l++) {
        pq[l] = *(const float4*)(Qh + (size_t)(m0 + am[l]) * PDH + ac4[l]);
        pk[l] = *(const float4*)(Kh + (size_t)(n0 + am[l]) * PDH + ac4[l]);
    }
#pragma unroll
    for (int l = 0; l < 2; l++) {
        As[0][ac4[l] + 0][am[l]] = pq[l].x; As[0][ac4[l] + 1][am[l]] = pq[l].y;
        As[0][ac4[l] + 2][am[l]] = pq[l].z; As[0][ac4[l] + 3][am[l]] = pq[l].w;
        Bs[0][ac4[l] + 0][am[l]] = pk[l].x; Bs[0][ac4[l] + 1][am[l]] = pk[l].y;
        Bs[0][ac4[l] + 2][am[l]] = pk[l].z; Bs[0][ac4[l] + 3][am[l]] = pk[l].w;
    }
    __syncthreads();

    const int NIT = PDH / 16;            // 4
    for (int it = 0; it < NIT; it++) {
        const int cur = it & 1;
        const bool hn = (it + 1 < NIT);
        if (hn) {
            int d0 = (it + 1) * 16;
#pragma unroll
            for (int l = 0; l < 2; l++) {
                pq[l] = *(const float4*)(Qh + (size_t)(m0 + am[l]) * PDH + d0 + ac4[l]);
                pk[l] = *(const float4*)(Kh + (size_t)(n0 + am[l]) * PDH + d0 + ac4[l]);
            }
        }
#pragma unroll
        for (int kk = 0; kk < 16; kk++) {
            float a[8];
            *(float4*)&a[0] = *(const float4*)&As[cur][kk][ty * 8];
            *(float4*)&a[4] = *(const float4*)&As[cur][kk][ty * 8 + 4];
            ulonglong2 bb0 = *(const ulonglong2*)&Bs[cur][kk][tx * 8];
            ulonglong2 bb1 = *(const ulonglong2*)&Bs[cur][kk][tx * 8 + 4];
            u64 b2[4] = {bb0.x, bb0.y, bb1.x, bb1.y};
            u64 a2[8];
#pragma unroll
            for (int i = 0; i < 8; i++) a2[i] = dup2(a[i]);
#pragma unroll
            for (int i = 0; i < 8; i++)
#pragma unroll
                for (int j2 = 0; j2 < 4; j2++) ffma2(acc[i][j2], a2[i], b2[j2]);
        }
        if (hn) {
            const int nxt = cur ^ 1;
#pragma unroll
            for (int l = 0; l < 2; l++) {
                As[nxt][ac4[l] + 0][am[l]] = pq[l].x; As[nxt][ac4[l] + 1][am[l]] = pq[l].y;
                As[nxt][ac4[l] + 2][am[l]] = pq[l].z; As[nxt][ac4[l] + 3][am[l]] = pq[l].w;
                Bs[nxt][ac4[l] + 0][am[l]] = pk[l].x; Bs[nxt][ac4[l] + 1][am[l]] = pk[l].y;
                Bs[nxt][ac4[l] + 2][am[l]] = pk[l].z; Bs[nxt][ac4[l] + 3][am[l]] = pk[l].w;
            }
        }
        __syncthreads();
    }

#pragma unroll
    for (int i = 0; i < 8; i++) {
        int qi = m0 + ty * 8 + i;
        float* dst = awb + (size_t)qi * PS + n0 + tx * 8;
        float o[8];
#pragma unroll
        for (int j2 = 0; j2 < 4; j2++) unpack2(acc[i][j2], o[2 * j2], o[2 * j2 + 1]);
        *(float4*)dst       = *(float4*)&o[0];
        *(float4*)(dst + 4) = *(float4*)&o[4];
    }
}

// ---------------------------------------------------------------------------
// Kernel 3: in-place row softmax over aws (memory bound; unchanged).
// ---------------------------------------------------------------------------
__global__ __launch_bounds__(256) void softmax_kernel(float* __restrict__ aw)
{
    float* p = aw + (size_t)blockIdx.x * PS;
    const int t = threadIdx.x;
    const int lane = t & 31, warp = t >> 5;

    float x[8];
    *(float4*)&x[0] = ((const float4*)p)[t];
    *(float4*)&x[4] = ((const float4*)p)[t + 256];

    float m = x[0];
#pragma unroll
    for (int i = 1; i < 8; i++) m = fmaxf(m, x[i]);
#pragma unroll
    for (int o = 16; o > 0; o >>= 1) m = fmaxf(m, __shfl_xor_sync(0xffffffffu, m, o));

    __shared__ float red[8];
    if (lane == 0) red[warp] = m;
    __syncthreads();
    float mm = red[0];
#pragma unroll
    for (int i = 1; i < 8; i++) mm = fmaxf(mm, red[i]);

    float ssum = 0.f;
#pragma unroll
    for (int i = 0; i < 8; i++) { x[i] = __expf(x[i] - mm); ssum += x[i]; }
#pragma unroll
    for (int o = 16; o > 0; o >>= 1) ssum += __shfl_xor_sync(0xffffffffu, ssum, o);

    __syncthreads();
    if (lane == 0) red[warp] = ssum;
    __syncthreads();
    float tot = 0.f;
#pragma unroll
    for (int i = 0; i < 8; i++) tot += red[i];
    float inv = 1.0f / tot;
#pragma unroll
    for (int i = 0; i < 8; i++) x[i] *= inv;

    ((float4*)p)[t]       = *(float4*)&x[0];
    ((float4*)p)[t + 256] = *(float4*)&x[4];
}

// ---------------------------------------------------------------------------
// Kernel 4: ctx = aw * V per (b,h). 128 threads/CTA, 8x8 per thread
// (1.0 B/FMA smem traffic, crossbar=fma balanced). j-packed FFMA2 with
// strided column-pairs (2*tx + 16*p) for conflict-free LDS.64 on V.
// ---------------------------------------------------------------------------
__global__ __launch_bounds__(128) void ctx_kernel(const float* __restrict__ aw)
{
    __shared__ float As[2][16][132];   // transposed aw tile: As[buf][kk][m]
    __shared__ float Bs[2][16][64];    // V tile, natural layout

    const int zz = blockIdx.z;
    const int b_ = zz >> 4, h_ = zz & 15;
    const float* awb = aw + (size_t)(h_ * PB + b_) * PS * PS;
    const float* Vh = g_V + (size_t)zz * PS * PDH;

    const int m0 = blockIdx.x * 128;
    const int tid = threadIdx.x;
    const int tx = tid & 7;            // 8 threads over N
    const int ty = tid >> 3;           // 16 threads over M

    // load coords: aw tile 128x16 = 512 float4, 4 per thread
    int am[4], ac4[4];
#pragma unroll
    for (int l = 0; l < 4; l++) {
        int f = tid + 128 * l;
        am[l] = f >> 2; ac4[l] = (f & 3) * 4;
    }
    // V tile 16x64 = 256 float4, 2 per thread
    int vkk[2], vc4[2];
#pragma unroll
    for (int l = 0; l < 2; l++) {
        int f = tid + 128 * l;
        vkk[l] = f >> 4; vc4[l] = (f & 15) * 4;
    }

    u64 acc[8][4];                  // [i][p]: rows ty*8+i, col-pair 2*tx+16*p
#pragma unroll
    for (int i = 0; i < 8; i++)
#pragma unroll
        for (int p = 0; p < 4; p++) acc[i][p] = 0ull;

    float4 pa[4], pv[2];
#pragma unroll
    for (int l = 0; l < 4; l++)
        pa[l] = *(const float4*)(awb + (size_t)(m0 + am[l]) * PS + ac4[l]);
#pragma unroll
    for (int l = 0; l < 2; l++)
        pv[l] = *(const float4*)(Vh + (size_t)vkk[l] * PDH + vc4[l]);
#pragma unroll
    for (int l = 0; l < 4; l++) {
        As[0][ac4[l] + 0][am[l]] = pa[l].x; As[0][ac4[l] + 1][am[l]] = pa[l].y;
        As[0][ac4[l] + 2][am[l]] = pa[l].z; As[0][ac4[l] + 3][am[l]] = pa[l].w;
    }
#pragma unroll
    for (int l = 0; l < 2; l++)
        *(float4*)&Bs[0][vkk[l]][vc4[l]] = pv[l];
    __syncthreads();

    const int NIT = PS / 16;          // 128
    for (int it = 0; it < NIT; it++) {
        const int cur = it & 1;
        const bool hn = (it + 1 < NIT);
        if (hn) {
            int kc = (it + 1) * 16;
#pragma unroll
            for (int l = 0; l < 4; l++)
                pa[l] = *(const float4*)(awb + (size_t)(m0 + am[l]) * PS + kc + ac4[l]);
#pragma unroll
            for (int l = 0; l < 2; l++)
                pv[l] = *(const float4*)(Vh + (size_t)(kc + vkk[l]) * PDH + vc4[l]);
        }
#pragma unroll
        for (int kk = 0; kk < 16; kk++) {
            float a[8];
            *(float4*)&a[0] = *(const float4*)&As[cur][kk][ty * 8];
            *(float4*)&a[4] = *(const float4*)&As[cur][kk][ty * 8 + 4];
            u64 a2[8];
#pragma unroll
            for (int i = 0; i < 8; i++) a2[i] = dup2(a[i]);
            u64 b2[4];
#pragma unroll
            for (int p = 0; p < 4; p++)
                b2[p] = *(const u64*)&Bs[cur][kk][2 * tx + 16 * p];
#pragma unroll
            for (int i = 0; i < 8; i++)
#pragma unroll
                for (int p = 0; p < 4; p++) ffma2(acc[i][p], a2[i], b2[p]);
        }
        if (hn) {
            const int nxt = cur ^ 1;
#pragma unroll
            for (int l = 0; l < 4; l++) {
                As[nxt][ac4[l] + 0][am[l]] = pa[l].x; As[nxt][ac4[l] + 1][am[l]] = pa[l].y;
                As[nxt][ac4[l] + 2][am[l]] = pa[l].z; As[nxt][ac4[l] + 3][am[l]] = pa[l].w;
            }
#pragma unroll
            for (int l = 0; l < 2; l++)
                *(float4*)&Bs[nxt][vkk[l]][vc4[l]] = pv[l];
        }
        __syncthreads();
    }

#pragma unroll
    for (int i = 0; i < 8; i++) {
        int s = m0 + ty * 8 + i;
        float* base = g_ctx + (size_t)(b_ * PS + s) * PD + h_ * PDH;
#pragma unroll
        for (int p = 0; p < 4; p++) {
            float lo, hi;
            unpack2(acc[i][p], lo, hi);
            *(float2*)(base + 2 * tx + 16 * p) = make_float2(lo, hi);
        }
    }
}

// ---------------------------------------------------------------------------
// Kernel 5: out = ctx @ Wo + bo. Double-buffered.
// ---------------------------------------------------------------------------
__global__ __launch_bounds__(256) void out_proj_kernel(
    const float* __restrict__ Wo, const float* __restrict__ bo,
    float* __restrict__ out)
{
    __shared__ float As[2][16][132];
    __shared__ float Bs[2][16][128];

    const int m0 = blockIdx.x * 128;
    const int n0 = blockIdx.y * 128;
    const int tid = threadIdx.x;
    const int tx = tid & 15, ty = tid >> 4;

    int am[2], ac4[2], bkk[2], bc4[2];
#pragma unroll
    for (int l = 0; l < 2; l++) {
        int f = tid + 256 * l;
        am[l] = f >> 2;  ac4[l] = (f & 3) * 4;
        bkk[l] = f >> 5; bc4[l] = (f & 31) * 4;
    }

    u64 acc[8][4];
#pragma unroll
    for (int i = 0; i < 8; i++)
#pragma unroll
        for (int j2 = 0; j2 < 4; j2++) acc[i][j2] = 0ull;

    float4 pa[2], pb[2];
#pragma unroll
    for (int l = 0; l < 2; l++) {
        pa[l] = *(const float4*)(g_ctx + (size_t)(m0 + am[l]) * PD + ac4[l]);
        pb[l] = *(const float4*)(Wo + (size_t)bkk[l] * PD + n0 + bc4[l]);
    }
#pragma unroll
    for (int l = 0; l < 2; l++) {
        As[0][ac4[l] + 0][am[l]] = pa[l].x; As[0][ac4[l] + 1][am[l]] = pa[l].y;
        As[0][ac4[l] + 2][am[l]] = pa[l].z; As[0][ac4[l] + 3][am[l]] = pa[l].w;
        *(float4*)&Bs[0][bkk[l]][bc4[l]] = pb[l];
    }
    __syncthreads();

    const int NIT = PD / 16;
    for (int it = 0; it < NIT; it++) {
        const int cur = it & 1;
        const bool hn = (it + 1 < NIT);
        if (hn) {
            int d0 = (it + 1) * 16;
#pragma unroll
            for (int l = 0; l < 2; l++) {
                pa[l] = *(const float4*)(g_ctx + (size_t)(m0 + am[l]) * PD + d0 + ac4[l]);
                pb[l] = *(const float4*)(Wo + (size_t)(d0 + bkk[l]) * PD + n0 + bc4[l]);
            }
        }
#pragma unroll
        for (int kk = 0; kk < 16; kk++) {
            float a[8];
            *(float4*)&a[0] = *(const float4*)&As[cur][kk][ty * 8];
            *(float4*)&a[4] = *(const float4*)&As[cur][kk][ty * 8 + 4];
            ulonglong2 bb0 = *(const ulonglong2*)&Bs[cur][kk][tx * 8];
            ulonglong2 bb1 = *(const ulonglong2*)&Bs[cur][kk][tx * 8 + 4];
            u64 b2[4] = {bb0.x, bb0.y, bb1.x, bb1.y};
            u64 a2[8];
#pragma unroll
            for (int i = 0; i < 8; i++) a2[i] = dup2(a[i]);
#pragma unroll
            for (int i = 0; i < 8; i++)
#pragma unroll
                for (int j2 = 0; j2 < 4; j2++) ffma2(acc[i][j2], a2[i], b2[j2]);
        }
        if (hn) {
            const int nxt = cur ^ 1;
#pragma unroll
            for (int l = 0; l < 2; l++) {
                As[nxt][ac4[l] + 0][am[l]] = pa[l].x; As[nxt][ac4[l] + 1][am[l]] = pa[l].y;
                As[nxt][ac4[l] + 2][am[l]] = pa[l].z; As[nxt][ac4[l] + 3][am[l]] = pa[l].w;
                *(float4*)&Bs[nxt][bkk[l]][bc4[l]] = pb[l];
            }
        }
        __syncthreads();
    }

    float bcol[8];
#pragma unroll
    for (int j = 0; j < 8; j++) bcol[j] = bo[n0 + tx * 8 + j];

#pragma unroll
    for (int i = 0; i < 8; i++) {
        int r = m0 + ty * 8 + i;
        float* dst = out + (size_t)r * PD + n0 + tx * 8;
        float o[8];
#pragma unroll
        for (int j2 = 0; j2 < 4; j2++) unpack2(acc[i][j2], o[2 * j2], o[2 * j2 + 1]);
#pragma unroll
        for (int j = 0; j < 8; j++) o[j] += bcol[j];
        *(float4*)dst       = *(float4*)&o[0];
        *(float4*)(dst + 4) = *(float4*)&o[4];
    }
}

// ---------------------------------------------------------------------------
extern "C" void kernel_launch(void* const* d_in, const int* in_sizes, int n_in,
                              void* d_out, int out_size)
{
    (void)in_sizes; (void)n_in; (void)out_size;
    const float* q  = (const float*)d_in[0];
    const float* k  = (const float*)d_in[1];
    const float* v  = (const float*)d_in[2];
    const float* Wq = (const float*)d_in[3];
    const float* Wk = (const float*)d_in[4];
    const float* Wv = (const float*)d_in[5];
    const float* bq = (const float*)d_in[6];
    const float* bk = (const float*)d_in[7];
    const float* bv = (const float*)d_in[8];
    const float* Wo = (const float*)d_in[9];
    const float* bo = (const float*)d_in[10];

    float* out = (float*)d_out;
    float* aw  = out + OUT_ELEMS;    // aws [H][B][S][S] follows out [B][S][D]

    qkv_proj_kernel<<<dim3(PBS / 128, PD / 128, 3), 256>>>(
        q, k, v, Wq, Wk, Wv, bq, bk, bv);
    scores_kernel<<<dim3(PS / 128, PS / 128, PB * PH), 256>>>(aw);
    softmax_kernel<<<PB * PH * PS, 256>>>(aw);
    ctx_kernel<<<dim3(PS / 128, 1, PB * PH), 128>>>(aw);
    out_proj_kernel<<<dim3(PBS / 128, PD / 128), 256>>>(Wo, bo, out);
}

// round 16
// speedup vs baseline: 1.0972x; 1.0009x over previous
#include <cuda_runtime.h>

// Problem constants
#define PB 2
#define PS 2048
#define PD 1024
#define PH 16
#define PDH 64
#define PBS (PB * PS)                        // 4096 rows
#define OUT_ELEMS ((long long)PB * PS * PD)  // 4194304

typedef unsigned long long u64;

// ---- packed fp32x2 helpers (Blackwell FFMA2 path) -------------------------
__device__ __forceinline__ u64 dup2(float x) {
    u64 r;
    asm("mov.b64 %0, {%1, %1};" : "=l"(r) : "f"(x));
    return r;
}
__device__ __forceinline__ void unpack2(u64 p, float& lo, float& hi) {
    asm("mov.b64 {%0, %1}, %2;" : "=f"(lo), "=f"(hi) : "l"(p));
}
__device__ __forceinline__ void ffma2(u64& d, u64 a, u64 b) {
    asm("fma.rn.f32x2 %0, %1, %2, %0;" : "+l"(d) : "l"(a), "l"(b));
}

// Scratch (device globals; no allocation allowed)
__device__ float g_Q[(size_t)PB * PH * PS * PDH];   // [b][h][s][k]
__device__ float g_K[(size_t)PB * PH * PS * PDH];
__device__ float g_V[(size_t)PB * PH * PS * PDH];
__device__ float g_ctx[(size_t)PB * PS * PD];       // [b][s][h*64+k]

// ---------------------------------------------------------------------------
// Kernel 1: fused Q/K/V per-head projections. Double-buffered smem pipeline.
// ---------------------------------------------------------------------------
__global__ __launch_bounds__(256) void qkv_proj_kernel(
    const float* __restrict__ q, const float* __restrict__ k,
    const float* __restrict__ v, const float* __restrict__ Wq,
    const float* __restrict__ Wk, const float* __restrict__ Wv,
    const float* __restrict__ bq, const float* __restrict__ bk,
    const float* __restrict__ bv)
{
    __shared__ float As[2][16][132];   // transposed: As[buf][kk][m]
    __shared__ float Bs[2][16][128];   // Bs[buf][kk][j]

    const int zz = blockIdx.z;
    const float* A    = (zz == 0) ? q  : (zz == 1) ? k  : v;
    const float* W    = (zz == 0) ? Wq : (zz == 1) ? Wk : Wv;
    const float* bias = (zz == 0) ? bq : (zz == 1) ? bk : bv;
    float* outp       = (zz == 0) ? g_Q : (zz == 1) ? g_K : g_V;
    const float scale = (zz == 0) ? 0.125f : 1.0f;   // 1/sqrt(DH) folded into Q

    const int m0 = blockIdx.x * 128;
    const int h0 = blockIdx.y * 2;
    const int tid = threadIdx.x;
    const int tx = tid & 15;
    const int ty = tid >> 4;

    // per-thread load coordinates (constant over K loop)
    int am[2], ac4[2], bkk[2], bc4[2], bhh[2], bkc[2];
#pragma unroll
    for (int l = 0; l < 2; l++) {
        int f = tid + 256 * l;
        am[l] = f >> 2;  ac4[l] = (f & 3) * 4;
        bkk[l] = f >> 5; bc4[l] = (f & 31) * 4;
        bhh[l] = h0 + (bc4[l] >> 6);
        bkc[l] = bc4[l] & 63;
    }

    u64 acc[8][4];
#pragma unroll
    for (int i = 0; i < 8; i++)
#pragma unroll
        for (int j2 = 0; j2 < 4; j2++) acc[i][j2] = 0ull;

    float4 pa[2], pb[2];
    // prologue: load tile 0
#pragma unroll
    for (int l = 0; l < 2; l++) {
        pa[l] = *(const float4*)(A + (size_t)(m0 + am[l]) * PD + ac4[l]);
        pb[l] = *(const float4*)(W + ((size_t)bhh[l] * PD + bkk[l]) * PDH + bkc[l]);
    }
#pragma unroll
    for (int l = 0; l < 2; l++) {
        As[0][ac4[l] + 0][am[l]] = pa[l].x; As[0][ac4[l] + 1][am[l]] = pa[l].y;
        As[0][ac4[l] + 2][am[l]] = pa[l].z; As[0][ac4[l] + 3][am[l]] = pa[l].w;
        *(float4*)&Bs[0][bkk[l]][bc4[l]] = pb[l];
    }
    __syncthreads();

    const int NIT = PD / 16;
    for (int it = 0; it < NIT; it++) {
        const int cur = it & 1;
        const bool hn = (it + 1 < NIT);
        if (hn) {
            int d0 = (it + 1) * 16;
#pragma unroll
            for (int l = 0; l < 2; l++) {
                pa[l] = *(const float4*)(A + (size_t)(m0 + am[l]) * PD + d0 + ac4[l]);
                pb[l] = *(const float4*)(W + ((size_t)bhh[l] * PD + d0 + bkk[l]) * PDH + bkc[l]);
            }
        }
#pragma unroll
        for (int kk = 0; kk < 16; kk++) {
            float a[8];
            *(float4*)&a[0] = *(const float4*)&As[cur][kk][ty * 8];
            *(float4*)&a[4] = *(const float4*)&As[cur][kk][ty * 8 + 4];
            ulonglong2 bb0 = *(const ulonglong2*)&Bs[cur][kk][tx * 8];
            ulonglong2 bb1 = *(const ulonglong2*)&Bs[cur][kk][tx * 8 + 4];
            u64 b2[4] = {bb0.x, bb0.y, bb1.x, bb1.y};
            u64 a2[8];
#pragma unroll
            for (int i = 0; i < 8; i++) a2[i] = dup2(a[i]);
#pragma unroll
            for (int i = 0; i < 8; i++)
#pragma unroll
                for (int j2 = 0; j2 < 4; j2++) ffma2(acc[i][j2], a2[i], b2[j2]);
        }
        if (hn) {
            const int nxt = cur ^ 1;
#pragma unroll
            for (int l = 0; l < 2; l++) {
                As[nxt][ac4[l] + 0][am[l]] = pa[l].x; As[nxt][ac4[l] + 1][am[l]] = pa[l].y;
                As[nxt][ac4[l] + 2][am[l]] = pa[l].z; As[nxt][ac4[l] + 3][am[l]] = pa[l].w;
                *(float4*)&Bs[nxt][bkk[l]][bc4[l]] = pb[l];
            }
        }
        __syncthreads();
    }

    const int jbase = tx * 8;
    const int hh = h0 + (jbase >> 6);
    const int kc0 = jbase & 63;
    float bcol[8];
#pragma unroll
    for (int j = 0; j < 8; j++) bcol[j] = bias[hh * PDH + kc0 + j];

#pragma unroll
    for (int i = 0; i < 8; i++) {
        int r = m0 + ty * 8 + i;
        int bb_ = r >> 11;
        int s = r & (PS - 1);
        float* dst = outp + ((size_t)(bb_ * PH + hh) * PS + s) * PDH + kc0;
        float o[8];
#pragma unroll
        for (int j2 = 0; j2 < 4; j2++) unpack2(acc[i][j2], o[2 * j2], o[2 * j2 + 1]);
#pragma unroll
        for (int j = 0; j < 8; j++) o[j] = (o[j] + bcol[j]) * scale;
        *(float4*)dst       = *(float4*)&o[0];
        *(float4*)(dst + 4) = *(float4*)&o[4];
    }
}

// ---------------------------------------------------------------------------
// Kernel 2: raw scores = Qh * Kh^T into aws[h][b][:, :]. Double-buffered.
// ---------------------------------------------------------------------------
__global__ __launch_bounds__(256) void scores_kernel(float* __restrict__ aw)
{
    __shared__ float As[2][16][132];
    __shared__ float Bs[2][16][132];

    const int zz = blockIdx.z;           // b*H + h
    const int b_ = zz >> 4, h_ = zz & 15;
    const float* Qh = g_Q + (size_t)zz * PS * PDH;
    const float* Kh = g_K + (size_t)zz * PS * PDH;
    float* awb = aw + (size_t)(h_ * PB + b_) * PS * PS;

    const int m0 = blockIdx.x * 128;
    const int n0 = blockIdx.y * 128;
    const int tid = threadIdx.x;
    const int tx = tid & 15, ty = tid >> 4;

    int am[2], ac4[2];
#pragma unroll
    for (int l = 0; l < 2; l++) {
        int f = tid + 256 * l;
        am[l] = f >> 2; ac4[l] = (f & 3) * 4;
    }

    u64 acc[8][4];
#pragma unroll
    for (int i = 0; i < 8; i++)
#pragma unroll
        for (int j2 = 0; j2 < 4; j2++) acc[i][j2] = 0ull;

    float4 pq[2], pk[2];
#pragma unroll
    for (int l = 0; l < 2; l++) {
        pq[l] = *(const float4*)(Qh + (size_t)(m0 + am[l]) * PDH + ac4[l]);
        pk[l] = *(const float4*)(Kh + (size_t)(n0 + am[l]) * PDH + ac4[l]);
    }
#pragma unroll
    for (int l = 0; l < 2; l++) {
        As[0][ac4[l] + 0][am[l]] = pq[l].x; As[0][ac4[l] + 1][am[l]] = pq[l].y;
        As[0][ac4[l] + 2][am[l]] = pq[l].z; As[0][ac4[l] + 3][am[l]] = pq[l].w;
        Bs[0][ac4[l] + 0][am[l]] = pk[l].x; Bs[0][ac4[l] + 1][am[l]] = pk[l].y;
        Bs[0][ac4[l] + 2][am[l]] = pk[l].z; Bs[0][ac4[l] + 3][am[l]] = pk[l].w;
    }
    __syncthreads();

    const int NIT = PDH / 16;            // 4
    for (int it = 0; it < NIT; it++) {
        const int cur = it & 1;
        const bool hn = (it + 1 < NIT);
        if (hn) {
            int d0 = (it + 1) * 16;
#pragma unroll
            for (int l = 0; l < 2; l++) {
                pq[l] = *(const float4*)(Qh + (size_t)(m0 + am[l]) * PDH + d0 + ac4[l]);
                pk[l] = *(const float4*)(Kh + (size_t)(n0 + am[l]) * PDH + d0 + ac4[l]);
            }
        }
#pragma unroll
        for (int kk = 0; kk < 16; kk++) {
            float a[8];
            *(float4*)&a[0] = *(const float4*)&As[cur][kk][ty * 8];
            *(float4*)&a[4] = *(const float4*)&As[cur][kk][ty * 8 + 4];
            ulonglong2 bb0 = *(const ulonglong2*)&Bs[cur][kk][tx * 8];
            ulonglong2 bb1 = *(const ulonglong2*)&Bs[cur][kk][tx * 8 + 4];
            u64 b2[4] = {bb0.x, bb0.y, bb1.x, bb1.y};
            u64 a2[8];
#pragma unroll
            for (int i = 0; i < 8; i++) a2[i] = dup2(a[i]);
#pragma unroll
            for (int i = 0; i < 8; i++)
#pragma unroll
                for (int j2 = 0; j2 < 4; j2++) ffma2(acc[i][j2], a2[i], b2[j2]);
        }
        if (hn) {
            const int nxt = cur ^ 1;
#pragma unroll
            for (int l = 0; l < 2; l++) {
                As[nxt][ac4[l] + 0][am[l]] = pq[l].x; As[nxt][ac4[l] + 1][am[l]] = pq[l].y;
                As[nxt][ac4[l] + 2][am[l]] = pq[l].z; As[nxt][ac4[l] + 3][am[l]] = pq[l].w;
                Bs[nxt][ac4[l] + 0][am[l]] = pk[l].x; Bs[nxt][ac4[l] + 1][am[l]] = pk[l].y;
                Bs[nxt][ac4[l] + 2][am[l]] = pk[l].z; Bs[nxt][ac4[l] + 3][am[l]] = pk[l].w;
            }
        }
        __syncthreads();
    }

#pragma unroll
    for (int i = 0; i < 8; i++) {
        int qi = m0 + ty * 8 + i;
        float* dst = awb + (size_t)qi * PS + n0 + tx * 8;
        float o[8];
#pragma unroll
        for (int j2 = 0; j2 < 4; j2++) unpack2(acc[i][j2], o[2 * j2], o[2 * j2 + 1]);
        *(float4*)dst       = *(float4*)&o[0];
        *(float4*)(dst + 4) = *(float4*)&o[4];
    }
}

// ---------------------------------------------------------------------------
// Kernel 3: in-place row softmax over aws (memory bound; unchanged).
// ---------------------------------------------------------------------------
__global__ __launch_bounds__(256) void softmax_kernel(float* __restrict__ aw)
{
    float* p = aw + (size_t)blockIdx.x * PS;
    const int t = threadIdx.x;
    const int lane = t & 31, warp = t >> 5;

    float x[8];
    *(float4*)&x[0] = ((const float4*)p)[t];
    *(float4*)&x[4] = ((const float4*)p)[t + 256];

    float m = x[0];
#pragma unroll
    for (int i = 1; i < 8; i++) m = fmaxf(m, x[i]);
#pragma unroll
    for (int o = 16; o > 0; o >>= 1) m = fmaxf(m, __shfl_xor_sync(0xffffffffu, m, o));

    __shared__ float red[8];
    if (lane == 0) red[warp] = m;
    __syncthreads();
    float mm = red[0];
#pragma unroll
    for (int i = 1; i < 8; i++) mm = fmaxf(mm, red[i]);

    float ssum = 0.f;
#pragma unroll
    for (int i = 0; i < 8; i++) { x[i] = __expf(x[i] - mm); ssum += x[i]; }
#pragma unroll
    for (int o = 16; o > 0; o >>= 1) ssum += __shfl_xor_sync(0xffffffffu, ssum, o);

    __syncthreads();
    if (lane == 0) red[warp] = ssum;
    __syncthreads();
    float tot = 0.f;
#pragma unroll
    for (int i = 0; i < 8; i++) tot += red[i];
    float inv = 1.0f / tot;
#pragma unroll
    for (int i = 0; i < 8; i++) x[i] *= inv;

    ((float4*)p)[t]       = *(float4*)&x[0];
    ((float4*)p)[t + 256] = *(float4*)&x[4];
}

// ---------------------------------------------------------------------------
// Kernel 4: ctx = aw * V per (b,h). 128 threads/CTA, 8x8 per thread
// (1.0 B/FMA smem traffic, crossbar=fma balanced). j-packed FFMA2 with
// strided column-pairs (2*tx + 16*p) for conflict-free LDS.64 on V.
// ---------------------------------------------------------------------------
__global__ __launch_bounds__(128) void ctx_kernel(const float* __restrict__ aw)
{
    __shared__ float As[2][16][132];   // transposed aw tile: As[buf][kk][m]
    __shared__ float Bs[2][16][64];    // V tile, natural layout

    const int zz = blockIdx.z;
    const int b_ = zz >> 4, h_ = zz & 15;
    const float* awb = aw + (size_t)(h_ * PB + b_) * PS * PS;
    const float* Vh = g_V + (size_t)zz * PS * PDH;

    const int m0 = blockIdx.x * 128;
    const int tid = threadIdx.x;
    const int tx = tid & 7;            // 8 threads over N
    const int ty = tid >> 3;           // 16 threads over M

    // load coords: aw tile 128x16 = 512 float4, 4 per thread
    int am[4], ac4[4];
#pragma unroll
    for (int l = 0; l < 4; l++) {
        int f = tid + 128 * l;
        am[l] = f >> 2; ac4[l] = (f & 3) * 4;
    }
    // V tile 16x64 = 256 float4, 2 per thread
    int vkk[2], vc4[2];
#pragma unroll
    for (int l = 0; l < 2; l++) {
        int f = tid + 128 * l;
        vkk[l] = f >> 4; vc4[l] = (f & 15) * 4;
    }

    u64 acc[8][4];                  // [i][p]: rows ty*8+i, col-pair 2*tx+16*p
#pragma unroll
    for (int i = 0; i < 8; i++)
#pragma unroll
        for (int p = 0; p < 4; p++) acc[i][p] = 0ull;

    float4 pa[4], pv[2];
#pragma unroll
    for (int l = 0; l < 4; l++)
        pa[l] = *(const float4*)(awb + (size_t)(m0 + am[l]) * PS + ac4[l]);
#pragma unroll
    for (int l = 0; l < 2; l++)
        pv[l] = *(const float4*)(Vh + (size_t)vkk[l] * PDH + vc4[l]);
#pragma unroll
    for (int l = 0; l < 4; l++) {
        As[0][ac4[l] + 0][am[l]] = pa[l].x; As[0][ac4[l] + 1][am[l]] = pa[l].y;
        As[0][ac4[l] + 2][am[l]] = pa[l].z; As[0][ac4[l] + 3][am[l]] = pa[l].w;
    }
#pragma unroll
    for (int l = 0; l < 2; l++)
        *(float4*)&Bs[0][vkk[l]][vc4[l]] = pv[l];
    __syncthreads();

    const int NIT = PS / 16;          // 128
    for (int it = 0; it < NIT; it++) {
        const int cur = it & 1;
        const bool hn = (it + 1 < NIT);
        if (hn) {
            int kc = (it + 1) * 16;
#pragma unroll
            for (int l = 0; l < 4; l++)
                pa[l] = *(const float4*)(awb + (size_t)(m0 + am[l]) * PS + kc + ac4[l]);
#pragma unroll
            for (int l = 0; l < 2; l++)
                pv[l] = *(const float4*)(Vh + (size_t)(kc + vkk[l]) * PDH + vc4[l]);
        }
#pragma unroll
        for (int kk = 0; kk < 16; kk++) {
            float a[8];
            *(float4*)&a[0] = *(const float4*)&As[cur][kk][ty * 8];
            *(float4*)&a[4] = *(const float4*)&As[cur][kk][ty * 8 + 4];
            u64 a2[8];
#pragma unroll
            for (int i = 0; i < 8; i++) a2[i] = dup2(a[i]);
            u64 b2[4];
#pragma unroll
            for (int p = 0; p < 4; p++)
                b2[p] = *(const u64*)&Bs[cur][kk][2 * tx + 16 * p];
#pragma unroll
            for (int i = 0; i < 8; i++)
#pragma unroll
                for (int p = 0; p < 4; p++) ffma2(acc[i][p], a2[i], b2[p]);
        }
        if (hn) {
            const int nxt = cur ^ 1;
#pragma unroll
            for (int l = 0; l < 4; l++) {
                As[nxt][ac4[l] + 0][am[l]] = pa[l].x; As[nxt][ac4[l] + 1][am[l]] = pa[l].y;
                As[nxt][ac4[l] + 2][am[l]] = pa[l].z; As[nxt][ac4[l] + 3][am[l]] = pa[l].w;
            }
#pragma unroll
            for (int l = 0; l < 2; l++)
                *(float4*)&Bs[nxt][vkk[l]][vc4[l]] = pv[l];
        }
        __syncthreads();
    }

#pragma unroll
    for (int i = 0; i < 8; i++) {
        int s = m0 + ty * 8 + i;
        float* base = g_ctx + (size_t)(b_ * PS + s) * PD + h_ * PDH;
#pragma unroll
        for (int p = 0; p < 4; p++) {
            float lo, hi;
            unpack2(acc[i][p], lo, hi);
            *(float2*)(base + 2 * tx + 16 * p) = make_float2(lo, hi);
        }
    }
}

// ---------------------------------------------------------------------------
// Kernel 5: out = ctx @ Wo + bo. Double-buffered.
// ---------------------------------------------------------------------------
__global__ __launch_bounds__(256) void out_proj_kernel(
    const float* __restrict__ Wo, const float* __restrict__ bo,
    float* __restrict__ out)
{
    __shared__ float As[2][16][132];
    __shared__ float Bs[2][16][128];

    const int m0 = blockIdx.x * 128;
    const int n0 = blockIdx.y * 128;
    const int tid = threadIdx.x;
    const int tx = tid & 15, ty = tid >> 4;

    int am[2], ac4[2], bkk[2], bc4[2];
#pragma unroll
    for (int l = 0; l < 2; l++) {
        int f = tid + 256 * l;
        am[l] = f >> 2;  ac4[l] = (f & 3) * 4;
        bkk[l] = f >> 5; bc4[l] = (f & 31) * 4;
    }

    u64 acc[8][4];
#pragma unroll
    for (int i = 0; i < 8; i++)
#pragma unroll
        for (int j2 = 0; j2 < 4; j2++) acc[i][j2] = 0ull;

    float4 pa[2], pb[2];
#pragma unroll
    for (int l = 0; l < 2; l++) {
        pa[l] = *(const float4*)(g_ctx + (size_t)(m0 + am[l]) * PD + ac4[l]);
        pb[l] = *(const float4*)(Wo + (size_t)bkk[l] * PD + n0 + bc4[l]);
    }
#pragma unroll
    for (int l = 0; l < 2; l++) {
        As[0][ac4[l] + 0][am[l]] = pa[l].x; As[0][ac4[l] + 1][am[l]] = pa[l].y;
        As[0][ac4[l] + 2][am[l]] = pa[l].z; As[0][ac4[l] + 3][am[l]] = pa[l].w;
        *(float4*)&Bs[0][bkk[l]][bc4[l]] = pb[l];
    }
    __syncthreads();

    const int NIT = PD / 16;
    for (int it = 0; it < NIT; it++) {
        const int cur = it & 1;
        const bool hn = (it + 1 < NIT);
        if (hn) {
            int d0 = (it + 1) * 16;
#pragma unroll
            for (int l = 0; l < 2; l++) {
                pa[l] = *(const float4*)(g_ctx + (size_t)(m0 + am[l]) * PD + d0 + ac4[l]);
                pb[l] = *(const float4*)(Wo + (size_t)(d0 + bkk[l]) * PD + n0 + bc4[l]);
            }
        }
#pragma unroll
        for (int kk = 0; kk < 16; kk++) {
            float a[8];
            *(float4*)&a[0] = *(const float4*)&As[cur][kk][ty * 8];
            *(float4*)&a[4] = *(const float4*)&As[cur][kk][ty * 8 + 4];
            ulonglong2 bb0 = *(const ulonglong2*)&Bs[cur][kk][tx * 8];
            ulonglong2 bb1 = *(const ulonglong2*)&Bs[cur][kk][tx * 8 + 4];
            u64 b2[4] = {bb0.x, bb0.y, bb1.x, bb1.y};
            u64 a2[8];
#pragma unroll
            for (int i = 0; i < 8; i++) a2[i] = dup2(a[i]);
#pragma unroll
            for (int i = 0; i < 8; i++)
#pragma unroll
                for (int j2 = 0; j2 < 4; j2++) ffma2(acc[i][j2], a2[i], b2[j2]);
        }
        if (hn) {
            const int nxt = cur ^ 1;
#pragma unroll
            for (int l = 0; l < 2; l++) {
                As[nxt][ac4[l] + 0][am[l]] = pa[l].x; As[nxt][ac4[l] + 1][am[l]] = pa[l].y;
                As[nxt][ac4[l] + 2][am[l]] = pa[l].z; As[nxt][ac4[l] + 3][am[l]] = pa[l].w;
                *(float4*)&Bs[nxt][bkk[l]][bc4[l]] = pb[l];
            }
        }
        __syncthreads();
    }

    float bcol[8];
#pragma unroll
    for (int j = 0; j < 8; j++) bcol[j] = bo[n0 + tx * 8 + j];

#pragma unroll
    for (int i = 0; i < 8; i++) {
        int r = m0 + ty * 8 + i;
        float* dst = out + (size_t)r * PD + n0 + tx * 8;
        float o[8];
#pragma unroll
        for (int j2 = 0; j2 < 4; j2++) unpack2(acc[i][j2], o[2 * j2], o[2 * j2 + 1]);
#pragma unroll
        for (int j = 0; j < 8; j++) o[j] += bcol[j];
        *(float4*)dst       = *(float4*)&o[0];
        *(float4*)(dst + 4) = *(float4*)&o[4];
    }
}

// ---------------------------------------------------------------------------
extern "C" void kernel_launch(void* const* d_in, const int* in_sizes, int n_in,
                              void* d_out, int out_size)
{
    (void)in_sizes; (void)n_in; (void)out_size;
    const float* q  = (const float*)d_in[0];
    const float* k  = (const float*)d_in[1];
    const float* v  = (const float*)d_in[2];
    const float* Wq = (const float*)d_in[3];
    const float* Wk = (const float*)d_in[4];
    const float* Wv = (const float*)d_in[5];
    const float* bq = (const float*)d_in[6];
    const float* bk = (const float*)d_in[7];
    const float* bv = (const float*)d_in[8];
    const float* Wo = (const float*)d_in[9];
    const float* bo = (const float*)d_in[10];

    float* out = (float*)d_out;
    float* aw  = out + OUT_ELEMS;    // aws [H][B][S][S] follows out [B][S][D]

    qkv_proj_kernel<<<dim3(PBS / 128, PD / 128, 3), 256>>>(
        q, k, v, Wq, Wk, Wv, bq, bk, bv);
    scores_kernel<<<dim3(PS / 128, PS / 128, PB * PH), 256>>>(aw);
    softmax_kernel<<<PB * PH * PS, 256>>>(aw);
    ctx_kernel<<<dim3(PS / 128, 1, PB * PH), 128>>>(aw);
    out_proj_kernel<<<dim3(PBS / 128, PD / 128), 256>>>(Wo, bo, out);
}